// round 15
// baseline (speedup 1.0000x reference)
#include <cuda_runtime.h>

// Problem constants (fixed by the reference)
#define BB 4
#define DD 64
#define KK 32
#define NN 8192            // T*H*W
#define TILE 1024          // elems per tile
#define TPR (NN / TILE)    // 8 tiles per (b,d) row
#define NTILE (BB * DD * TPR)   // 2048 tiles
#define TPB 256

typedef unsigned long long u64;

// Scratch (no allocations allowed): per-tile partial sums of E
__device__ float g_part[NTILE];

// ---- packed f32x2 helpers (sm_103a) --------------------------------------
__device__ __forceinline__ u64 pk2(float lo, float hi) {
    u64 r; asm("mov.b64 %0, {%1, %2};" : "=l"(r) : "f"(lo), "f"(hi)); return r;
}
__device__ __forceinline__ void up2(u64 v, float& lo, float& hi) {
    asm("mov.b64 {%0, %1}, %2;" : "=f"(lo), "=f"(hi) : "l"(v));
}
__device__ __forceinline__ u64 fma2_(u64 a, u64 b, u64 c) {
    u64 r; asm("fma.rn.f32x2 %0, %1, %2, %3;" : "=l"(r) : "l"(a), "l"(b), "l"(c)); return r;
}
__device__ __forceinline__ u64 add2_(u64 a, u64 b) {
    u64 r; asm("add.rn.f32x2 %0, %1, %2;" : "=l"(r) : "l"(a), "l"(b)); return r;
}
__device__ __forceinline__ u64 mul2_(u64 a, u64 b) {
    u64 r; asm("mul.rn.f32x2 %0, %1, %2;" : "=l"(r) : "l"(a), "l"(b)); return r;
}
__device__ __forceinline__ float fex2(float x) {
    float y; asm("ex2.approx.ftz.f32 %0, %1;" : "=f"(y) : "f"(x)); return y;
}
__device__ __forceinline__ float frcp(float x) {
    float y; asm("rcp.approx.ftz.f32 %0, %1;" : "=f"(y) : "f"(x)); return y;
}
__device__ __forceinline__ u64 ex2_2(u64 a) {        // MUFU path (2 x XU)
    float lo, hi; up2(a, lo, hi);
    return pk2(fex2(lo), fex2(hi));
}

// Packed 2^t on the FMA pipe. Valid for t in (-126, 1): here t in [-47, ~0].
// t = i + f via magic-constant round-to-nearest; 2^f deg-5 Taylor; 2^i by
// exponent-bit insertion (ALU pipe).
struct PolyC {
    u64 MAG, NMAG, N1, C5, C4, C3, C2, C1, C0;
};
__device__ __forceinline__ u64 exp2_poly2(u64 t, const PolyC& pc) {
    const u64 m = add2_(t, pc.MAG);          // RN(t) stashed in mantissa
    const u64 i = add2_(m, pc.NMAG);         // i = round(t), exact
    const u64 f = fma2_(i, pc.N1, t);        // f = t - i, exact, in [-0.5,0.5]
    u64 p = fma2_(pc.C5, f, pc.C4);
    p = fma2_(p, f, pc.C3);
    p = fma2_(p, f, pc.C2);
    p = fma2_(p, f, pc.C1);
    p = fma2_(p, f, pc.C0);
    // exponent scale: bits(m_half) = 0x4B400000 + i  ->  (bits<<23)+127<<23 = bits of 2^i
    unsigned mlo, mhi;
    asm("mov.b64 {%0, %1}, %2;" : "=r"(mlo), "=r"(mhi) : "l"(m));
    const unsigned elo = (mlo << 23) + 0x3F800000u;
    const unsigned ehi = (mhi << 23) + 0x3F800000u;
    u64 e; asm("mov.b64 %0, {%1, %2};" : "=l"(e) : "r"(elo), "r"(ehi));
    return mul2_(p, e);
}

// ---------------------------------------------------------------------------
// Kernel A: per-tile encode.
//   E[b,d,n] = (x*den - cn) / den,  den = sum_k e_k,  cn = sum_k e_k*c_k,
//   e_k = 2^(A_k x^2 + B_k x + C_k)   with A=s*log2e, B=-2Ac, C=Ac^2
// Hybrid exp: pair0 always MUFU ex2; pair1 alternates MUFU / fma-poly by k
// parity -> MUFU and FMA pipes co-saturated.
// Writes unscaled E to out, per-tile partial sum to g_part[tile].
// Grid: NTILE blocks x 256 threads (1 float4 each).
// ---------------------------------------------------------------------------
__global__ __launch_bounds__(TPB) void k_encode(
    const float* __restrict__ X,
    const float* __restrict__ cw,
    const float* __restrict__ sc,
    float* __restrict__ out)
{
    __shared__ ulonglong2 sAB[KK];   // {A,A},{B,B}
    __shared__ ulonglong2 sCc[KK];   // {C,C},{c,c}
    __shared__ float s_red[8];

    const int tid = threadIdx.x;
    const int bid = blockIdx.x;
    const int bd  = bid >> 3;            // (b*DD + d)
    const int j   = bid & (TPR - 1);
    const int d   = bd & (DD - 1);

    if (tid < KK) {
        const float s = sc[tid * DD + d] * 1.4426950408889634f;
        const float c = cw[tid * DD + d];
        const float Bq = -2.0f * s * c;
        const float Cq = s * c * c;
        sAB[tid] = make_ulonglong2(pk2(s, s), pk2(Bq, Bq));
        sCc[tid] = make_ulonglong2(pk2(Cq, Cq), pk2(c, c));
    }
    __syncthreads();

    PolyC pc;
    pc.MAG  = pk2( 12582912.0f,  12582912.0f);
    pc.NMAG = pk2(-12582912.0f, -12582912.0f);
    pc.N1   = pk2(-1.0f, -1.0f);
    pc.C5   = pk2(0.0013333558f, 0.0013333558f);
    pc.C4   = pk2(0.0096181291f, 0.0096181291f);
    pc.C3   = pk2(0.0555041087f, 0.0555041087f);
    pc.C2   = pk2(0.2402265070f, 0.2402265070f);
    pc.C1   = pk2(0.6931471806f, 0.6931471806f);
    pc.C0   = pk2(1.0f, 1.0f);

    const size_t base = (size_t)bd * NN + (size_t)j * TILE;
    const float4 x4 = reinterpret_cast<const float4*>(X + base)[tid];
    const u64 xp0 = pk2(x4.x, x4.y);
    const u64 xp1 = pk2(x4.z, x4.w);

    u64 den0 = 0ull, den1 = 0ull;      // bit pattern == (0.f, 0.f)
    u64 cn0  = 0ull, cn1  = 0ull;

    #pragma unroll
    for (int k = 0; k < KK; k++) {
        const ulonglong2 ab  = sAB[k];     // LDS.128 broadcast
        const ulonglong2 ccv = sCc[k];     // LDS.128 broadcast
        const u64 t0 = fma2_(ab.x, xp0, ab.y);
        const u64 a0 = fma2_(t0,  xp0, ccv.x);
        const u64 t1 = fma2_(ab.x, xp1, ab.y);
        const u64 a1 = fma2_(t1,  xp1, ccv.x);
        const u64 e0 = ex2_2(a0);                              // MUFU
        const u64 e1 = (k & 1) ? exp2_poly2(a1, pc)            // FMA pipe
                               : ex2_2(a1);                    // MUFU
        den0 = add2_(den0, e0);
        den1 = add2_(den1, e1);
        cn0  = fma2_(e0, ccv.y, cn0);
        cn1  = fma2_(e1, ccv.y, cn1);
    }

    float d0, d1, d2, d3, c0, c1, c2v, c3;
    up2(den0, d0, d1); up2(den1, d2, d3);
    up2(cn0,  c0, c1); up2(cn1,  c2v, c3);
    const float E0 = fmaf(x4.x, d0, -c0 ) * frcp(d0);
    const float E1 = fmaf(x4.y, d1, -c1 ) * frcp(d1);
    const float E2 = fmaf(x4.z, d2, -c2v) * frcp(d2);
    const float E3 = fmaf(x4.w, d3, -c3 ) * frcp(d3);
    reinterpret_cast<float4*>(out + base)[tid] = make_float4(E0, E1, E2, E3);

    // ---- deterministic block reduce -> per-tile partial ----
    float psum = (E0 + E1) + (E2 + E3);
    #pragma unroll
    for (int o = 16; o > 0; o >>= 1)
        psum += __shfl_xor_sync(0xffffffffu, psum, o);
    if ((tid & 31) == 0) s_red[tid >> 5] = psum;
    __syncthreads();
    if (tid == 0) {
        float t = 0.f;
        #pragma unroll
        for (int i = 0; i < 8; i++) t += s_red[i];
        g_part[bid] = t;
    }
}

// ---------------------------------------------------------------------------
// Kernel B: per-tile finish.
//   Eglob[b,e] = (1/K) * sum_j g_part[(b*DD+e)*TPR + j]
//   gamma      = sigmoid(Eglob[b,:] . fc_w[d,:] + fc_b[d])   (per-block, tiny)
//   out        = relu(out * (1 + gamma))   in place
// Grid: NTILE blocks x 256 threads.
// ---------------------------------------------------------------------------
__global__ __launch_bounds__(TPB) void k_finish(
    const float* __restrict__ fw,
    const float* __restrict__ fb,
    float* __restrict__ out)
{
    __shared__ float s_dot[DD];
    __shared__ float s_gs;

    const int tid = threadIdx.x;
    const int bid = blockIdx.x;
    const int bd  = bid >> 3;
    const int j   = bid & (TPR - 1);
    const int b   = bd >> 6;
    const int d   = bd & (DD - 1);

    if (tid < DD) {
        const float* pp = g_part + (size_t)((b << 6) + tid) * TPR;
        const float s = ((pp[0] + pp[1]) + (pp[2] + pp[3]))
                      + ((pp[4] + pp[5]) + (pp[6] + pp[7]));
        s_dot[tid] = (s * (1.0f / KK)) * fw[d * DD + tid];
    }
    __syncthreads();
    if (tid == 0) {
        float acc = fb[d];
        #pragma unroll
        for (int e = 0; e < DD; e++) acc += s_dot[e];
        // 1 + sigmoid(acc)
        s_gs = 1.0f + frcp(1.0f + fex2(-acc * 1.4426950408889634f));
    }
    __syncthreads();
    const float gs = s_gs;

    const size_t base = (size_t)bd * NN + (size_t)j * TILE;
    float4* p = reinterpret_cast<float4*>(out + base);
    float4 v = p[tid];
    v.x = fmaxf(v.x * gs, 0.f);
    v.y = fmaxf(v.y * gs, 0.f);
    v.z = fmaxf(v.z * gs, 0.f);
    v.w = fmaxf(v.w * gs, 0.f);
    p[tid] = v;
}

// ---------------------------------------------------------------------------
extern "C" void kernel_launch(void* const* d_in, const int* in_sizes, int n_in,
                              void* d_out, int out_size)
{
    (void)in_sizes; (void)n_in; (void)out_size;
    const float* X  = (const float*)d_in[0];  // (B, D, T, H, W)
    const float* cw = (const float*)d_in[1];  // (K, D)
    const float* sc = (const float*)d_in[2];  // (K, D)
    const float* fw = (const float*)d_in[3];  // (D, D)
    const float* fb = (const float*)d_in[4];  // (D,)
    float* out = (float*)d_out;               // (B, D, T, H, W)

    k_encode<<<NTILE, TPB>>>(X, cw, sc, out);
    k_finish<<<NTILE, TPB>>>(fw, fb, out);
}